// round 1
// baseline (speedup 1.0000x reference)
#include <cuda_runtime.h>
#include <cstdint>
#include <math.h>

// ---------------------------------------------------------------------------
// SpikingNet: 100-step LIF RNN, batch 4096, 784 -> 100 -> 10.
// Per step: xi = U(key_t) * x   (JAX threefry, partitionable mode, bit-exact)
//           layer1: e1 = xi@W1+b1; inner1 = e1 + 0.9*prev; outer1 = relu(inner1-1)
//                   if outer1>0: inner1 -= 1.5*inner1
//           layer2 input is the PREVIOUS step's outer1 (delayed) -> no intra-step
//           dependency between layer1 and layer2 => single kernel per step.
//           collect inner2_new for steps t in [19, 98]; final log_softmax.
// ---------------------------------------------------------------------------

#define DEV_INLINE __device__ __forceinline__

constexpr int BATCH = 4096;
constexpr int NIN   = 784;
constexpr int H1    = 100;
constexpr int H2    = 10;
constexpr int TSTEP = 100;

constexpr int ROWS  = 16;              // batch rows per CTA
constexpr int CTAS  = BATCH / ROWS;    // 256
constexpr int NTHR  = 200;             // 8 row-threads x 25 col-threads
constexpr int APAD  = 17;              // smem A panel row pad (bank-conflict free)
constexpr int SMEM_BYTES = NIN * APAD * (int)sizeof(float);  // 53312 B

// ----------------------------- state ---------------------------------------
__device__ float g_inner1[BATCH * H1];
__device__ float g_outer1[2][BATCH * H1];   // double buffered (delayed output)
__device__ float g_inner2[BATCH * H2];
__device__ float g_acc[BATCH * H2];

// --------------------------- threefry2x32 (20 rounds) -----------------------
DEV_INLINE uint2 threefry2x32(uint32_t k0, uint32_t k1, uint32_t x0, uint32_t x1) {
    uint32_t ks2 = k0 ^ k1 ^ 0x1BD11BDAu;
    x0 += k0; x1 += k1;
#define TF_R(r) { x0 += x1; x1 = __funnelshift_l(x1, x1, (r)); x1 ^= x0; }
    TF_R(13) TF_R(15) TF_R(26) TF_R(6)   x0 += k1;  x1 += ks2 + 1u;
    TF_R(17) TF_R(29) TF_R(16) TF_R(24)  x0 += ks2; x1 += k0  + 2u;
    TF_R(13) TF_R(15) TF_R(26) TF_R(6)   x0 += k0;  x1 += k1  + 3u;
    TF_R(17) TF_R(29) TF_R(16) TF_R(24)  x0 += k1;  x1 += ks2 + 4u;
    TF_R(13) TF_R(15) TF_R(26) TF_R(6)   x0 += ks2; x1 += k0  + 5u;
#undef TF_R
    return make_uint2(x0, x1);
}

// ----------------------------- zero init ------------------------------------
__global__ void zero_state_kernel() {
    int i = blockIdx.x * blockDim.x + threadIdx.x;
    int stride = gridDim.x * blockDim.x;
    for (int k = i; k < BATCH * H1; k += stride) {
        g_inner1[k] = 0.f;
        g_outer1[0][k] = 0.f;
        g_outer1[1][k] = 0.f;
    }
    for (int k = i; k < BATCH * H2; k += stride) {
        g_inner2[k] = 0.f;
        g_acc[k] = 0.f;
    }
}

// ----------------------------- per-step kernel -------------------------------
__global__ void __launch_bounds__(NTHR, 2)
step_kernel(const float* __restrict__ x,
            const float* __restrict__ W1,
            const float* __restrict__ b1,
            const float* __restrict__ W2,
            const float* __restrict__ b2,
            int t)
{
    extern __shared__ float A_s[];   // [NIN][APAD] : gated inputs for this CTA's rows
    const int tid  = threadIdx.x;
    const int row0 = blockIdx.x * ROWS;

    // ---------------- layer 2 (reads PREVIOUS step's outer1) ----------------
    {
        const float* __restrict__ po1 = g_outer1[(t & 1) ^ 1];
        const bool collect = (t >= 19 && t <= 98);
        for (int o = tid; o < ROWS * H2; o += NTHR) {
            const int r = row0 + o / H2;
            const int j = o % H2;
            float acc = b2[j];
            const float* prow = po1 + r * H1;
            #pragma unroll 4
            for (int h = 0; h < H1; ++h)
                acc = fmaf(prow[h], W2[h * H2 + j], acc);
            const int gi = r * H2 + j;
            float inner = __fadd_rn(acc, __fmul_rn(g_inner2[gi], 0.9f));
            float outer = inner - 1.0f;
            float nin;
            if (outer > 0.0f) nin = __fsub_rn(inner, __fmul_rn(1.5f, inner));
            else              nin = inner;
            g_inner2[gi] = nin;
            if (collect) g_acc[gi] += nin;
        }
    }

    // ---------------- RNG: fill gated-input panel into smem -----------------
    // subkey[t] = threefry((0,42),(0,t))  (fold-like split, partitionable mode)
    {
        const uint2 sk = threefry2x32(0u, 42u, 0u, (uint32_t)t);
        const uint32_t k0 = sk.x, k1 = sk.y;
        for (int e = tid; e < ROWS * NIN; e += NTHR) {
            const int r = e / NIN;
            const int f = e - r * NIN;
            const uint32_t idx = (uint32_t)((row0 + r) * NIN + f);
            const uint2 o = threefry2x32(k0, k1, 0u, idx);   // counter hi=0, lo=idx
            const uint32_t bits = o.x ^ o.y;                 // partitionable fold
            const float u = __uint_as_float((bits >> 9) | 0x3f800000u) - 1.0f;
            A_s[f * APAD + r] = u * x[(row0 + r) * NIN + f];
        }
    }
    __syncthreads();

    // ---------------- layer 1 GEMM + LIF epilogue ---------------------------
    // thread (tm in [0,8), tn in [0,25)): rows {2tm, 2tm+1}, cols {4tn..4tn+3}
    const int tn = tid % 25;
    const int tm = tid / 25;
    float a00 = 0.f, a01 = 0.f, a02 = 0.f, a03 = 0.f;
    float a10 = 0.f, a11 = 0.f, a12 = 0.f, a13 = 0.f;
    const float4* __restrict__ W1v = (const float4*)W1;   // W1 row = 25 float4s

    #pragma unroll 1
    for (int k0i = 0; k0i < NIN; k0i += 8) {
        #pragma unroll
        for (int u = 0; u < 8; ++u) {
            const int k = k0i + u;
            const float av0 = A_s[k * APAD + 2 * tm];
            const float av1 = A_s[k * APAD + 2 * tm + 1];
            const float4 w = W1v[k * 25 + tn];
            a00 = fmaf(av0, w.x, a00);
            a01 = fmaf(av0, w.y, a01);
            a02 = fmaf(av0, w.z, a02);
            a03 = fmaf(av0, w.w, a03);
            a10 = fmaf(av1, w.x, a10);
            a11 = fmaf(av1, w.y, a11);
            a12 = fmaf(av1, w.z, a12);
            a13 = fmaf(av1, w.w, a13);
        }
    }

    float* __restrict__ co1 = g_outer1[t & 1];
    float accs[2][4] = {{a00, a01, a02, a03}, {a10, a11, a12, a13}};
    #pragma unroll
    for (int rr = 0; rr < 2; ++rr) {
        const int row = row0 + 2 * tm + rr;
        float* pin  = g_inner1 + row * H1;
        float* pout = co1      + row * H1;
        #pragma unroll
        for (int cc = 0; cc < 4; ++cc) {
            const int j = 4 * tn + cc;
            const float e1 = __fadd_rn(accs[rr][cc], b1[j]);
            const float inner = __fadd_rn(e1, __fmul_rn(pin[j], 0.9f));
            float outer = inner - 1.0f;
            outer = outer > 0.0f ? outer : 0.0f;
            pout[j] = outer;
            float nin;
            if (outer > 0.0f) nin = __fsub_rn(inner, __fmul_rn(1.5f, inner));
            else              nin = inner;
            pin[j] = nin;
        }
    }
}

// ----------------------------- log_softmax ----------------------------------
__global__ void finalize_kernel(float* __restrict__ out) {
    const int b = blockIdx.x * blockDim.x + threadIdx.x;
    if (b >= BATCH) return;
    float v[H2];
    float m = -INFINITY;
    #pragma unroll
    for (int j = 0; j < H2; ++j) {
        v[j] = g_acc[b * H2 + j];
        m = fmaxf(m, v[j]);
    }
    float s = 0.f;
    #pragma unroll
    for (int j = 0; j < H2; ++j) s += expf(v[j] - m);
    const float l = logf(s);
    #pragma unroll
    for (int j = 0; j < H2; ++j) out[b * H2 + j] = v[j] - m - l;
}

// ----------------------------- launch ---------------------------------------
extern "C" void kernel_launch(void* const* d_in, const int* in_sizes, int n_in,
                              void* d_out, int out_size)
{
    const float* x  = (const float*)d_in[0];
    const float* W1 = (const float*)d_in[1];
    const float* b1 = (const float*)d_in[2];
    const float* W2 = (const float*)d_in[3];
    const float* b2 = (const float*)d_in[4];
    float* out = (float*)d_out;

    cudaFuncSetAttribute(step_kernel,
                         cudaFuncAttributeMaxDynamicSharedMemorySize, SMEM_BYTES);

    zero_state_kernel<<<256, 256>>>();
    for (int t = 0; t < TSTEP; ++t)
        step_kernel<<<CTAS, NTHR, SMEM_BYTES>>>(x, W1, b1, W2, b2, t);
    finalize_kernel<<<(BATCH + 255) / 256, 256>>>(out);
}

// round 5
// speedup vs baseline: 1.3901x; 1.3901x over previous
#include <cuda_runtime.h>
#include <cstdint>
#include <math.h>

// ---------------------------------------------------------------------------
// SpikingNet: 100-step LIF RNN, batch 4096, 784 -> 100 -> 10.
// R2: ROWS=8 / grid=512 / 64-thread CTAs; per-thread 8x2 register tile
// (16 accs, 84% FMA density); W double-buffer prefetch (8 deep) to hide L2;
// A panel [k][8 rows] in smem: conflict-free STS.128 writes, broadcast reads.
// ---------------------------------------------------------------------------

#define DEV_INLINE __device__ __forceinline__

constexpr int BATCH = 4096;
constexpr int NIN   = 784;
constexpr int H1    = 100;
constexpr int H2    = 10;
constexpr int TSTEP = 100;

constexpr int ROWS  = 8;               // batch rows per CTA
constexpr int CTAS  = BATCH / ROWS;    // 512
constexpr int NTHR  = 64;              // 2 warps; warp w covers cols [w*64, w*64+64)

// ----------------------------- state ---------------------------------------
__device__ float g_inner1[BATCH * H1];
__device__ float g_outer1[2][BATCH * H1];   // double buffered (delayed output)
__device__ float g_inner2[BATCH * H2];
__device__ float g_acc[BATCH * H2];

// --------------------------- threefry2x32 (20 rounds) -----------------------
DEV_INLINE uint2 threefry2x32(uint32_t k0, uint32_t k1, uint32_t x0, uint32_t x1) {
    uint32_t ks2 = k0 ^ k1 ^ 0x1BD11BDAu;
    x0 += k0; x1 += k1;
#define TF_R(r) { x0 += x1; x1 = __funnelshift_l(x1, x1, (r)); x1 ^= x0; }
    TF_R(13) TF_R(15) TF_R(26) TF_R(6)   x0 += k1;  x1 += ks2 + 1u;
    TF_R(17) TF_R(29) TF_R(16) TF_R(24)  x0 += ks2; x1 += k0  + 2u;
    TF_R(13) TF_R(15) TF_R(26) TF_R(6)   x0 += k0;  x1 += k1  + 3u;
    TF_R(17) TF_R(29) TF_R(16) TF_R(24)  x0 += k1;  x1 += ks2 + 4u;
    TF_R(13) TF_R(15) TF_R(26) TF_R(6)   x0 += ks2; x1 += k0  + 5u;
#undef TF_R
    return make_uint2(x0, x1);
}

DEV_INLINE float tf_uniform(uint32_t k0, uint32_t k1, uint32_t idx) {
    const uint2 o = threefry2x32(k0, k1, 0u, idx);
    const uint32_t bits = o.x ^ o.y;                 // partitionable fold
    return __uint_as_float((bits >> 9) | 0x3f800000u) - 1.0f;
}

// ----------------------------- zero init ------------------------------------
__global__ void zero_state_kernel() {
    int i = blockIdx.x * blockDim.x + threadIdx.x;
    int stride = gridDim.x * blockDim.x;
    for (int k = i; k < BATCH * H1; k += stride) {
        g_inner1[k] = 0.f;
        g_outer1[0][k] = 0.f;
        g_outer1[1][k] = 0.f;
    }
    for (int k = i; k < BATCH * H2; k += stride) {
        g_inner2[k] = 0.f;
        g_acc[k] = 0.f;
    }
}

// ----------------------------- per-step kernel -------------------------------
__global__ void __launch_bounds__(NTHR)
step_kernel(const float* __restrict__ x,
            const float* __restrict__ W1,
            const float* __restrict__ b1,
            const float* __restrict__ W2,
            const float* __restrict__ b2,
            int t)
{
    __shared__ float4 As4[NIN * 2];     // [k][chunk] : chunk0 = rows 0-3, chunk1 = rows 4-7
    const int tid  = threadIdx.x;
    const int row0 = blockIdx.x * ROWS;

    // ---------------- layer 2 (reads PREVIOUS step's outer1) ----------------
    {
        const float* __restrict__ po1 = g_outer1[(t & 1) ^ 1];
        const bool collect = (t >= 19 && t <= 98);
        for (int o = tid; o < ROWS * H2; o += NTHR) {
            const int r = row0 + o / H2;
            const int j = o % H2;
            float acc = b2[j];
            const float4* __restrict__ prow4 = (const float4*)(po1 + r * H1);
            #pragma unroll
            for (int h4 = 0; h4 < 25; ++h4) {
                const float4 p = prow4[h4];
                const int hb = h4 * 4;
                acc = fmaf(p.x, W2[(hb + 0) * H2 + j], acc);
                acc = fmaf(p.y, W2[(hb + 1) * H2 + j], acc);
                acc = fmaf(p.z, W2[(hb + 2) * H2 + j], acc);
                acc = fmaf(p.w, W2[(hb + 3) * H2 + j], acc);
            }
            const int gi = r * H2 + j;
            float inner = __fadd_rn(acc, __fmul_rn(g_inner2[gi], 0.9f));
            float outer = inner - 1.0f;
            float nin;
            if (outer > 0.0f) nin = __fsub_rn(inner, __fmul_rn(1.5f, inner));
            else              nin = inner;
            g_inner2[gi] = nin;
            if (collect) g_acc[gi] += nin;
        }
    }

    // ---------------- RNG: fill gated-input panel into smem -----------------
    // quad q: f = q>>1, chunk = q&1 (rows chunk*4 .. chunk*4+3); 4-way ILP.
    {
        const uint2 sk = threefry2x32(0u, 42u, 0u, (uint32_t)t);
        const uint32_t k0 = sk.x, k1 = sk.y;
        for (int q = tid; q < NIN * 2; q += NTHR) {
            const int f     = q >> 1;
            const int chunk = q & 1;
            const int grow  = row0 + chunk * 4;
            const uint32_t base = (uint32_t)(grow * NIN + f);
            const float u0 = tf_uniform(k0, k1, base);
            const float u1 = tf_uniform(k0, k1, base + NIN);
            const float u2 = tf_uniform(k0, k1, base + 2 * NIN);
            const float u3 = tf_uniform(k0, k1, base + 3 * NIN);
            As4[q] = make_float4(u0 * x[base],
                                 u1 * x[base + NIN],
                                 u2 * x[base + 2 * NIN],
                                 u3 * x[base + 3 * NIN]);
        }
    }
    __syncthreads();

    // ---------------- layer 1 GEMM + LIF epilogue ---------------------------
    // warp w covers cols [w*64, w*64+64); lane l -> cols j0 = w*64 + 2l.
    // Each thread: 8 rows x 2 cols (16 accs). Cols >= 100 clamped & discarded.
    const int warp = tid >> 5;
    const int lane = tid & 31;
    const int j0   = warp * 64 + lane * 2;
    const int j0c  = j0 <= 98 ? j0 : 98;           // clamp (even, in-bounds)
    const float2* __restrict__ Wp = (const float2*)(W1) + (j0c >> 1);  // row k: Wp[k*50]

    float accA[8], accB[8];                         // accA: col j0, accB: col j0+1
    #pragma unroll
    for (int r = 0; r < 8; ++r) { accA[r] = 0.f; accB[r] = 0.f; }

    float2 wb[8];
    #pragma unroll
    for (int u = 0; u < 8; ++u) wb[u] = Wp[u * 50];

#define GEMM_BLOCK(K0)                                                        \
    _Pragma("unroll")                                                         \
    for (int u = 0; u < 8; ++u) {                                             \
        const int kk = (K0) + u;                                              \
        const float4 a0 = As4[kk * 2];                                        \
        const float4 a1 = As4[kk * 2 + 1];                                    \
        accA[0] = fmaf(a0.x, wb[u].x, accA[0]);                               \
        accB[0] = fmaf(a0.x, wb[u].y, accB[0]);                               \
        accA[1] = fmaf(a0.y, wb[u].x, accA[1]);                               \
        accB[1] = fmaf(a0.y, wb[u].y, accB[1]);                               \
        accA[2] = fmaf(a0.z, wb[u].x, accA[2]);                               \
        accB[2] = fmaf(a0.z, wb[u].y, accB[2]);                               \
        accA[3] = fmaf(a0.w, wb[u].x, accA[3]);                               \
        accB[3] = fmaf(a0.w, wb[u].y, accB[3]);                               \
        accA[4] = fmaf(a1.x, wb[u].x, accA[4]);                               \
        accB[4] = fmaf(a1.x, wb[u].y, accB[4]);                               \
        accA[5] = fmaf(a1.y, wb[u].x, accA[5]);                               \
        accB[5] = fmaf(a1.y, wb[u].y, accB[5]);                               \
        accA[6] = fmaf(a1.z, wb[u].x, accA[6]);                               \
        accB[6] = fmaf(a1.z, wb[u].y, accB[6]);                               \
        accA[7] = fmaf(a1.w, wb[u].x, accA[7]);                               \
        accB[7] = fmaf(a1.w, wb[u].y, accB[7]);                               \
    }

    #pragma unroll 1
    for (int k0i = 0; k0i < NIN - 8; k0i += 8) {
        float2 wn[8];
        #pragma unroll
        for (int u = 0; u < 8; ++u) wn[u] = Wp[(k0i + 8 + u) * 50];  // prefetch
        GEMM_BLOCK(k0i)
        #pragma unroll
        for (int u = 0; u < 8; ++u) wb[u] = wn[u];
    }
    GEMM_BLOCK(NIN - 8)
#undef GEMM_BLOCK

    // epilogue: LIF update for this thread's 8 rows x 2 cols (if j0 < 100)
    if (j0 < H1) {
        const float bA = b1[j0], bB = b1[j0 + 1];
        float* __restrict__ co1 = g_outer1[t & 1];
        #pragma unroll
        for (int r = 0; r < 8; ++r) {
            const int row = row0 + r;
            float* pin  = g_inner1 + row * H1 + j0;
            float* pout = co1      + row * H1 + j0;

            const float e1A = __fadd_rn(accA[r], bA);
            const float innerA = __fadd_rn(e1A, __fmul_rn(pin[0], 0.9f));
            float outerA = innerA - 1.0f;
            outerA = outerA > 0.0f ? outerA : 0.0f;
            float ninA;
            if (outerA > 0.0f) ninA = __fsub_rn(innerA, __fmul_rn(1.5f, innerA));
            else               ninA = innerA;

            const float e1B = __fadd_rn(accB[r], bB);
            const float innerB = __fadd_rn(e1B, __fmul_rn(pin[1], 0.9f));
            float outerB = innerB - 1.0f;
            outerB = outerB > 0.0f ? outerB : 0.0f;
            float ninB;
            if (outerB > 0.0f) ninB = __fsub_rn(innerB, __fmul_rn(1.5f, innerB));
            else               ninB = innerB;

            pin[0]  = ninA;  pin[1]  = ninB;
            pout[0] = outerA; pout[1] = outerB;
        }
    }
}

// ----------------------------- log_softmax ----------------------------------
__global__ void finalize_kernel(float* __restrict__ out) {
    const int b = blockIdx.x * blockDim.x + threadIdx.x;
    if (b >= BATCH) return;
    float v[H2];
    float m = -INFINITY;
    #pragma unroll
    for (int j = 0; j < H2; ++j) {
        v[j] = g_acc[b * H2 + j];
        m = fmaxf(m, v[j]);
    }
    float s = 0.f;
    #pragma unroll
    for (int j = 0; j < H2; ++j) s += expf(v[j] - m);
    const float l = logf(s);
    #pragma unroll
    for (int j = 0; j < H2; ++j) out[b * H2 + j] = v[j] - m - l;
}

// ----------------------------- launch ---------------------------------------
extern "C" void kernel_launch(void* const* d_in, const int* in_sizes, int n_in,
                              void* d_out, int out_size)
{
    const float* x  = (const float*)d_in[0];
    const float* W1 = (const float*)d_in[1];
    const float* b1 = (const float*)d_in[2];
    const float* W2 = (const float*)d_in[3];
    const float* b2 = (const float*)d_in[4];
    float* out = (float*)d_out;

    zero_state_kernel<<<256, 256>>>();
    for (int t = 0; t < TSTEP; ++t)
        step_kernel<<<CTAS, NTHR>>>(x, W1, b1, W2, b2, t);
    finalize_kernel<<<(BATCH + 255) / 256, 256>>>(out);
}